// round 13
// baseline (speedup 1.0000x reference)
#include <cuda_runtime.h>
#include <math.h>

#define HW 16384
#define N_ANCH 147456

__device__ float g_rpn[512 * HW];
__device__ float g_score[N_ANCH];
__device__ int g_hist[65536];
__device__ int g_hist2[65536];
__device__ unsigned g_b16;
__device__ int g_cntabove;
__device__ unsigned g_thr32;
__device__ int g_candcnt;
__device__ unsigned long long g_cand[4096];
__device__ int g_selidx[2048];
__device__ float g_selscore[2048];
__device__ float g_props[2048 * 4];
__device__ float g_area[2048];
__device__ unsigned g_validw[64];
__device__ unsigned g_supmask[2048 * 64];
__device__ unsigned g_keepw[64];
__device__ int g_keepcnt;

__global__ void k_init() {
    int t = blockIdx.x * 1024 + threadIdx.x;
    if (t < 65536) { g_hist[t] = 0; g_hist2[t] = 0; }
    if (t < 64) g_validw[t] = 0u;
    if (t == 0) g_candcnt = 0;
}

__global__ void k_nop() {}

// 3x3 conv 512->512 over 128x128, bias+relu.
// grid(256 half-rows, 4 oc-groups), block 256, 2 blocks/SM.
// Per-output FMA sequence is bit-identical to the R10/R12 passing version
// (icb 127..0, icr A/B split at 6, w0/w1/w2 order, (accA+accB)+b) — DO NOT TOUCH.
// Tile is 64 px x 128 oc (8 oc x 4 px per thread, 64 accum regs) so two blocks
// fit per SM without spills: better wave balance + smem-phase/FMA overlap.
__global__ __launch_bounds__(256, 2) void k_conv(const float* __restrict__ feat,
                                                 const float* __restrict__ w,
                                                 const float* __restrict__ bias) {
    __shared__ float s_w[36 * 129];
    __shared__ float s_f[12 * 68];
    int y = blockIdx.x >> 1;
    int x0 = (blockIdx.x & 1) * 64;
    int oc0 = blockIdx.y * 128;
    int t = threadIdx.x;
    int tx = t & 15;
    int toc = t >> 4;

    float accA[8][4], accB[8][4];
#pragma unroll
    for (int i = 0; i < 8; i++)
#pragma unroll
        for (int j = 0; j < 4; j++) { accA[i][j] = 0.f; accB[i][j] = 0.f; }

    for (int icb = 127; icb >= 0; icb--) {
#pragma unroll
        for (int k = 0; k < 18; k++) {
            int idx = t + 256 * k;
            int oc = idx / 36, r = idx - oc * 36;
            s_w[r * 129 + oc] = w[(oc0 + oc) * 4608 + icb * 36 + r];
        }
        // feature tile: 12 rows x 66 cols (x0-1 .. x0+64), u = gx - x0 + 1
#pragma unroll
        for (int k = 0; k < 4; k++) {
            int idx = t + 256 * k;
            if (idx < 792) {
                int icr = idx / 66;
                int u = idx - icr * 66;
                int gx = x0 + u - 1;
                int icL = icr / 3;
                int ky = icr - icL * 3;
                int gy = y + ky - 1;
                float v = 0.f;
                if (gy >= 0 && gy < 128 && gx >= 0 && gx < 128)
                    v = feat[(icb * 4 + icL) * HW + gy * 128 + gx];
                s_f[icr * 68 + u] = v;
            }
        }
        __syncthreads();

#pragma unroll 4
        for (int icr = 0; icr < 12; icr++) {
            float f0[4], f1[4], f2[4];
            int fb = icr * 68 + tx;
#pragma unroll
            for (int j = 0; j < 4; j++) {
                f0[j] = s_f[fb + 16 * j];
                f1[j] = s_f[fb + 16 * j + 1];
                f2[j] = s_f[fb + 16 * j + 2];
            }
            int wb = 3 * icr * 129 + toc;
#pragma unroll
            for (int i = 0; i < 8; i++) {
                float w0 = s_w[wb + 16 * i];
                float w1 = s_w[wb + 129 + 16 * i];
                float w2 = s_w[wb + 258 + 16 * i];
                if (icr < 6) {
#pragma unroll
                    for (int j = 0; j < 4; j++) {
                        accA[i][j] = fmaf(w0, f0[j], accA[i][j]);
                        accA[i][j] = fmaf(w1, f1[j], accA[i][j]);
                        accA[i][j] = fmaf(w2, f2[j], accA[i][j]);
                    }
                } else {
#pragma unroll
                    for (int j = 0; j < 4; j++) {
                        accB[i][j] = fmaf(w0, f0[j], accB[i][j]);
                        accB[i][j] = fmaf(w1, f1[j], accB[i][j]);
                        accB[i][j] = fmaf(w2, f2[j], accB[i][j]);
                    }
                }
            }
        }
        __syncthreads();
    }
#pragma unroll
    for (int i = 0; i < 8; i++) {
        int oc = oc0 + toc + 16 * i;
        float b = bias[oc];
#pragma unroll
        for (int j = 0; j < 4; j++) {
            float v = (accA[i][j] + accB[i][j]) + b;
            g_rpn[oc * HW + y * 128 + x0 + tx + 16 * j] = fmaxf(v, 0.f);
        }
    }
}

// 1x1 cls head (512->9) in FP64 + sigmoid + coarse 16-bit histogram. grid 128, block 128.
// VERBATIM from the R10 passing kernel — load-bearing for the knife-edge decisions.
__global__ __launch_bounds__(128) void k_cls(const float* __restrict__ cw,
                                             const float* __restrict__ cb) {
    __shared__ double s_cw[512 * 9];
    int y = blockIdx.x, x = threadIdx.x;
#pragma unroll
    for (int k = 0; k < 36; k++) {
        int idx = x + 128 * k;
        int a = idx >> 9, c = idx & 511;
        s_cw[c * 9 + a] = (double)cw[idx];
    }
    __syncthreads();
    double acc[9];
#pragma unroll
    for (int a = 0; a < 9; a++) acc[a] = (double)cb[a];
    int pos = y * 128 + x;
#pragma unroll 2
    for (int c = 0; c < 512; c++) {
        double v = (double)g_rpn[c * HW + pos];
#pragma unroll
        for (int a = 0; a < 9; a++) acc[a] = fma(v, s_cw[c * 9 + a], acc[a]);
    }
#pragma unroll
    for (int a = 0; a < 9; a++) {
        float s = (float)(1.0 / (1.0 + exp(-acc[a])));
        g_score[pos * 9 + a] = s;
        atomicAdd(&g_hist[__float_as_uint(s) >> 16], 1);
    }
}

// coarse pass: parallel suffix-scan to find the 16-bit bucket containing rank 2000.
__global__ __launch_bounds__(1024) void k_thresh() {
    __shared__ int s_c[1024];
    __shared__ int warp_tot[32];
    int t = threadIdx.x;
    const int4* p = (const int4*)g_hist + t * 16;
    int s = 0;
#pragma unroll
    for (int i = 0; i < 16; i++) { int4 v = p[i]; s += v.x + v.y + v.z + v.w; }
    s_c[t] = s;
    __syncthreads();
    int k = 1023 - t;
    int val = s_c[k];
    int lane = t & 31, wid = t >> 5;
#pragma unroll
    for (int o = 1; o < 32; o <<= 1) {
        int n = __shfl_up_sync(0xFFFFFFFFu, val, o);
        if (lane >= o) val += n;
    }
    if (lane == 31) warp_tot[wid] = val;
    __syncthreads();
    if (wid == 0) {
        int wv = warp_tot[lane];
#pragma unroll
        for (int o = 1; o < 32; o <<= 1) {
            int n = __shfl_up_sync(0xFFFFFFFFu, wv, o);
            if (lane >= o) wv += n;
        }
        warp_tot[lane] = wv;
    }
    __syncthreads();
    int S_incl = val + (wid > 0 ? warp_tot[wid - 1] : 0);
    int S_next = S_incl - s_c[k];
    if (S_incl >= 2000 && S_next < 2000) {
        int a2 = S_next;
        unsigned B = 0;
        for (int b = 63; b >= 0; b--) {
            int c = g_hist[k * 64 + b];
            if (a2 + c >= 2000) { B = (unsigned)(k * 64 + b); break; }
            a2 += c;
        }
        g_b16 = B; g_cntabove = a2;
    }
}

// fine pass: histogram low 16 bits within the boundary bucket.
__global__ void k_hist2() {
    int idx = blockIdx.x * 256 + threadIdx.x;
    if (idx >= N_ANCH) return;
    unsigned bits = __float_as_uint(g_score[idx]);
    if ((bits >> 16) == g_b16) atomicAdd(&g_hist2[bits & 0xFFFFu], 1);
}

// refine to exact 32-bit threshold (parallel suffix-scan).
__global__ __launch_bounds__(1024) void k_thresh2() {
    __shared__ int s_c[1024];
    __shared__ int warp_tot[32];
    int t = threadIdx.x;
    const int4* p = (const int4*)g_hist2 + t * 16;
    int s = 0;
#pragma unroll
    for (int i = 0; i < 16; i++) { int4 v = p[i]; s += v.x + v.y + v.z + v.w; }
    s_c[t] = s;
    __syncthreads();
    int k = 1023 - t;
    int val = s_c[k];
    int lane = t & 31, wid = t >> 5;
#pragma unroll
    for (int o = 1; o < 32; o <<= 1) {
        int n = __shfl_up_sync(0xFFFFFFFFu, val, o);
        if (lane >= o) val += n;
    }
    if (lane == 31) warp_tot[wid] = val;
    __syncthreads();
    if (wid == 0) {
        int wv = warp_tot[lane];
#pragma unroll
        for (int o = 1; o < 32; o <<= 1) {
            int n = __shfl_up_sync(0xFFFFFFFFu, wv, o);
            if (lane >= o) wv += n;
        }
        warp_tot[lane] = wv;
    }
    __syncthreads();
    int target = 2000 - g_cntabove;
    int S_incl = val + (wid > 0 ? warp_tot[wid - 1] : 0);
    int S_next = S_incl - s_c[k];
    if (S_incl >= target && S_next < target) {
        int a2 = S_next;
        unsigned L = 0;
        for (int b = 63; b >= 0; b--) {
            int c = g_hist2[k * 64 + b];
            if (a2 + c >= target) { L = (unsigned)(k * 64 + b); break; }
            a2 += c;
        }
        g_thr32 = (g_b16 << 16) | L;
    }
}

__global__ void k_gather() {
    int idx = blockIdx.x * 256 + threadIdx.x;
    if (idx >= N_ANCH) return;
    unsigned bits = __float_as_uint(g_score[idx]);
    if (bits >= g_thr32) {
        int p = atomicAdd(&g_candcnt, 1);
        if (p < 4096)
            g_cand[p] = ((unsigned long long)bits << 32) | (unsigned)(~(unsigned)idx);
    }
}

__global__ __launch_bounds__(1024) void k_sort() {
    __shared__ unsigned long long s[4096];
    int t = threadIdx.x;
    int cnt = g_candcnt; if (cnt > 4096) cnt = 4096;
    for (int i = t; i < 4096; i += 1024) s[i] = (i < cnt) ? g_cand[i] : 0ULL;
    __syncthreads();
    for (int k = 2; k <= 4096; k <<= 1) {
        for (int j = k >> 1; j > 0; j >>= 1) {
            for (int i = t; i < 4096; i += 1024) {
                int ixj = i ^ j;
                if (ixj > i) {
                    unsigned long long a = s[i], b = s[ixj];
                    bool up = (i & k) == 0;
                    if (up ? (a < b) : (a > b)) { s[i] = b; s[ixj] = a; }
                }
            }
            __syncthreads();
        }
    }
    for (int r = t; r < 2000; r += 1024) {
        unsigned long long key = s[r];
        g_selscore[r] = __uint_as_float((unsigned)(key >> 32));
        g_selidx[r] = (int)(~(unsigned)key);
    }
}

// per-selected-box: FP64 4x 512-dot (box head) + exact-f32 anchor decode chain
__global__ __launch_bounds__(256) void k_decode(const float* __restrict__ bw,
                                                const float* __restrict__ bb) {
    int warp = threadIdx.x >> 5;
    int lane = threadIdx.x & 31;
    int r = blockIdx.x * 8 + warp;
    if (r >= 2000) return;
    int idx = g_selidx[r];
    int pidx = idx / 9;
    int a = idx - pidx * 9;
    const float* w0 = bw + (4 * a + 0) * 512;
    const float* w1 = bw + (4 * a + 1) * 512;
    const float* w2 = bw + (4 * a + 2) * 512;
    const float* w3 = bw + (4 * a + 3) * 512;
    double s0 = 0.0, s1 = 0.0, s2 = 0.0, s3 = 0.0;
    for (int c = lane; c < 512; c += 32) {
        double v = (double)g_rpn[c * HW + pidx];
        s0 = fma(v, (double)w0[c], s0);
        s1 = fma(v, (double)w1[c], s1);
        s2 = fma(v, (double)w2[c], s2);
        s3 = fma(v, (double)w3[c], s3);
    }
#pragma unroll
    for (int o = 16; o > 0; o >>= 1) {
        s0 += __shfl_xor_sync(0xFFFFFFFFu, s0, o);
        s1 += __shfl_xor_sync(0xFFFFFFFFu, s1, o);
        s2 += __shfl_xor_sync(0xFFFFFFFFu, s2, o);
        s3 += __shfl_xor_sync(0xFFFFFFFFu, s3, o);
    }
    if (lane == 0) {
        float dx = (float)(s0 + (double)bb[4 * a + 0]);
        float dy = (float)(s1 + (double)bb[4 * a + 1]);
        float dw = (float)(s2 + (double)bb[4 * a + 2]);
        float dh = (float)(s3 + (double)bb[4 * a + 3]);
        int ari = a / 3, si = a - ari * 3;
        float arf = (ari == 0) ? 0.5f : ((ari == 1) ? 1.0f : 2.0f);
        float scf = (si == 0) ? 128.f : ((si == 1) ? 256.f : 512.f);
        float h_r = __fsqrt_rn(arf);
        float w_r = __fdiv_rn(1.0f, h_r);
        float ws = __fmul_rn(w_r, scf), hs = __fmul_rn(h_r, scf);
        float bx1 = rintf(__fmul_rn(-0.5f, ws)), bx2 = rintf(__fmul_rn(0.5f, ws));
        float by1 = rintf(__fmul_rn(-0.5f, hs)), by2 = rintf(__fmul_rn(0.5f, hs));
        int gy = pidx >> 7, gx = pidx & 127;
        float sx = (float)(gx * 16), sy = (float)(gy * 16);
        float x1 = __fadd_rn(sx, bx1), y1 = __fadd_rn(sy, by1);
        float x2 = __fadd_rn(sx, bx2), y2 = __fadd_rn(sy, by2);
        float aw = __fsub_rn(x2, x1), ah = __fsub_rn(y2, y1);
        float acx = __fadd_rn(x1, __fmul_rn(0.5f, aw));
        float acy = __fadd_rn(y1, __fmul_rn(0.5f, ah));
        const float BCLIP = 4.135166556742356f;
        dw = fminf(dw, BCLIP);
        dh = fminf(dh, BCLIP);
        float pcx = __fadd_rn(__fmul_rn(dx, aw), acx);
        float pcy = __fadd_rn(__fmul_rn(dy, ah), acy);
        float ew = (float)exp((double)dw);
        float eh = (float)exp((double)dh);
        float pw = __fmul_rn(ew, aw);
        float ph = __fmul_rn(eh, ah);
        float x1p = __fsub_rn(pcx, __fmul_rn(0.5f, pw));
        float y1p = __fsub_rn(pcy, __fmul_rn(0.5f, ph));
        float x2p = __fadd_rn(pcx, __fmul_rn(0.5f, pw));
        float y2p = __fadd_rn(pcy, __fmul_rn(0.5f, ph));
        float x1c = fminf(fmaxf(x1p, 0.f), 2048.f);
        float y1c = fminf(fmaxf(y1p, 0.f), 2048.f);
        float x2c = fminf(fmaxf(x2p, 0.f), 2048.f);
        float y2c = fminf(fmaxf(y2p, 0.f), 2048.f);
        float wsz = __fsub_rn(x2c, x1c), hsz = __fsub_rn(y2c, y1c);
        g_props[r * 4 + 0] = x1c;
        g_props[r * 4 + 1] = y1c;
        g_props[r * 4 + 2] = x2c;
        g_props[r * 4 + 3] = y2c;
        g_area[r] = __fmul_rn(wsz, hsz);
        if (wsz >= 16.0f && hsz >= 16.0f)
            atomicOr(&g_validw[r >> 5], 1u << (r & 31));
    }
}

// 2000x2000 IoU>0.7 bitmatrix, exact f32 op chain. grid(63,63), block(32,32).
__global__ void k_iou() {
    __shared__ float4 sbi[32], sbj[32];
    __shared__ float sai[32], saj[32];
    int tx = threadIdx.x, ty = threadIdx.y;
    int i0 = blockIdx.y * 32, j0 = blockIdx.x * 32;
    if (ty == 0) { sbj[tx] = ((const float4*)g_props)[j0 + tx]; saj[tx] = g_area[j0 + tx]; }
    if (ty == 1) { sbi[tx] = ((const float4*)g_props)[i0 + tx]; sai[tx] = g_area[i0 + tx]; }
    __syncthreads();
    float4 bi = sbi[ty], bj = sbj[tx];
    float x1 = fmaxf(bi.x, bj.x), y1 = fmaxf(bi.y, bj.y);
    float x2 = fminf(bi.z, bj.z), y2 = fminf(bi.w, bj.w);
    float iw_ = fmaxf(__fsub_rn(x2, x1), 0.f);
    float ih_ = fmaxf(__fsub_rn(y2, y1), 0.f);
    float inter = __fmul_rn(iw_, ih_);
    float uni = fmaxf(__fsub_rn(__fadd_rn(sai[ty], saj[tx]), inter), 1e-9f);
    unsigned m = __ballot_sync(0xFFFFFFFFu, __fdiv_rn(inter, uni) > 0.7f);
    if (tx == 0) g_supmask[(i0 + ty) * 64 + blockIdx.x] = m;
}

// sequential greedy NMS on bitmatrix; one warp, keep mask in registers.
__global__ void k_nms() {
    int lane = threadIdx.x;
    unsigned keep0 = 0, keep1 = 0;
    unsigned valid0 = g_validw[lane], valid1 = g_validw[lane + 32];
    unsigned sup0 = g_supmask[lane], sup1 = g_supmask[lane + 32];
    for (int i = 0; i < 2000; i++) {
        unsigned n0 = 0, n1 = 0;
        if (i < 1999) {
            n0 = g_supmask[(i + 1) * 64 + lane];
            n1 = g_supmask[(i + 1) * 64 + lane + 32];
        }
        int w = i >> 5;
        unsigned bmask = (1u << (i & 31)) - 1u;
        unsigned below0 = (lane < w) ? 0xFFFFFFFFu : ((lane == w) ? bmask : 0u);
        unsigned below1 = ((lane + 32) < w) ? 0xFFFFFFFFu : (((lane + 32) == w) ? bmask : 0u);
        unsigned tbits = (sup0 & keep0 & below0) | (sup1 & keep1 & below1);
        bool suppressed = __any_sync(0xFFFFFFFFu, tbits != 0u);
        if (!suppressed) {
            unsigned bit = 1u << (i & 31);
            if (w < 32) { if (lane == w && (valid0 & bit)) keep0 |= bit; }
            else        { if (lane == w - 32 && (valid1 & bit)) keep1 |= bit; }
        }
        sup0 = n0; sup1 = n1;
    }
    g_keepw[lane] = keep0;
    g_keepw[lane + 32] = keep1;
    int c = __popc(keep0) + __popc(keep1);
#pragma unroll
    for (int o = 16; o > 0; o >>= 1) c += __shfl_xor_sync(0xFFFFFFFFu, c, o);
    if (lane == 0) g_keepcnt = c;
}

// compact kept boxes into output: props[0..4000), scores[4000..5000)
__global__ __launch_bounds__(1024) void k_final(float* __restrict__ out) {
    __shared__ int pre[64];
    __shared__ unsigned kw[64];
    int t = threadIdx.x;
    if (t < 64) kw[t] = g_keepw[t];
    __syncthreads();
    if (t == 0) {
        int acc = 0;
        for (int wds = 0; wds < 64; wds++) { pre[wds] = acc; acc += __popc(kw[wds]); }
    }
    __syncthreads();
    int K = g_keepcnt;
    for (int r = t; r < 2000; r += 1024) {
        int w = r >> 5, b = r & 31;
        if ((kw[w] >> b) & 1u) {
            int rank = pre[w] + __popc(kw[w] & ((1u << b) - 1u));
            if (rank < 1000) {
                out[rank * 4 + 0] = g_props[r * 4 + 0];
                out[rank * 4 + 1] = g_props[r * 4 + 1];
                out[rank * 4 + 2] = g_props[r * 4 + 2];
                out[rank * 4 + 3] = g_props[r * 4 + 3];
                out[4000 + rank] = g_selscore[r];
            }
        }
    }
    for (int k = t; k < 1000; k += 1024) {
        if (k >= K) {
            out[k * 4 + 0] = 0.f;
            out[k * 4 + 1] = 0.f;
            out[k * 4 + 2] = 0.f;
            out[k * 4 + 3] = 0.f;
            out[4000 + k] = -1.0f;
        }
    }
}

extern "C" void kernel_launch(void* const* d_in, const int* in_sizes, int n_in,
                              void* d_out, int out_size) {
    const float* feat   = (const float*)d_in[1];
    const float* conv_w = (const float*)d_in[2];
    const float* conv_b = (const float*)d_in[3];
    const float* cls_w  = (const float*)d_in[4];
    const float* cls_b  = (const float*)d_in[5];
    const float* box_w  = (const float*)d_in[6];
    const float* box_b  = (const float*)d_in[7];
    float* out = (float*)d_out;

    k_init<<<64, 1024>>>();
    // 2 no-op launches so k_conv is the 4th launch (empirically the one ncu captures)
    k_nop<<<1, 32>>>();
    k_nop<<<1, 32>>>();
    k_conv<<<dim3(256, 4), 256>>>(feat, conv_w, conv_b);
    k_cls<<<128, 128>>>(cls_w, cls_b);
    k_thresh<<<1, 1024>>>();
    k_hist2<<<(N_ANCH + 255) / 256, 256>>>();
    k_thresh2<<<1, 1024>>>();
    k_gather<<<(N_ANCH + 255) / 256, 256>>>();
    k_sort<<<1, 1024>>>();
    k_decode<<<250, 256>>>(box_w, box_b);
    k_iou<<<dim3(63, 63), dim3(32, 32)>>>();
    k_nms<<<1, 32>>>();
    k_final<<<1, 1024>>>(out);
}

// round 14
// speedup vs baseline: 1.4199x; 1.4199x over previous
#include <cuda_runtime.h>
#include <math.h>

#define HW 16384
#define N_ANCH 147456

__device__ float g_rpn[512 * HW];
__device__ float g_score[N_ANCH];
__device__ int g_hist[65536];
__device__ int g_hist2[65536];
__device__ unsigned g_b16;
__device__ int g_cntabove;
__device__ unsigned g_thr32;
__device__ int g_candcnt;
__device__ unsigned long long g_cand[4096];
__device__ int g_selidx[2048];
__device__ float g_selscore[2048];
__device__ float g_props[2048 * 4];
__device__ float g_area[2048];
__device__ unsigned g_validw[64];
__device__ unsigned g_supmask[2048 * 64];
__device__ unsigned g_keepw[64];
__device__ int g_keepcnt;

__global__ void k_init() {
    int t = blockIdx.x * 1024 + threadIdx.x;
    if (t < 65536) { g_hist[t] = 0; g_hist2[t] = 0; }
    if (t < 64) g_validw[t] = 0u;
    if (t == 0) g_candcnt = 0;
}

__global__ void k_nop() {}

// 3x3 conv 512->512 over 128x128, bias+relu.
// grid(128 rows, 8 oc-groups of 64), block 128 (16 px-phases x 8 oc-phases), 2 blocks/SM.
// Per-thread tile stays 8oc x 8px (4:1 FMA:LDS — the R13 half-px tile broke this).
// Per-output FMA sequence bit-identical to R10/R12 passing versions
// (icb 127..0, icr A/B split at 6, w0/w1/w2 order, (accA+accB)+b) — DO NOT TOUCH.
__global__ __launch_bounds__(128, 2) void k_conv(const float* __restrict__ feat,
                                                 const float* __restrict__ w,
                                                 const float* __restrict__ bias) {
    __shared__ float s_w[36 * 65];
    __shared__ float s_f[12 * 130];
    int y = blockIdx.x;
    int oc0 = blockIdx.y * 64;
    int t = threadIdx.x;
    int tx = t & 15;
    int toc = t >> 4;   // 0..7

    float accA[8][8], accB[8][8];
#pragma unroll
    for (int i = 0; i < 8; i++)
#pragma unroll
        for (int j = 0; j < 8; j++) { accA[i][j] = 0.f; accB[i][j] = 0.f; }

    for (int icb = 127; icb >= 0; icb--) {
        // weights: 64 oc x 36 (4ic x 9 taps) = 2304 floats
#pragma unroll
        for (int k = 0; k < 18; k++) {
            int idx = t + 128 * k;
            int oc = idx / 36, r = idx - oc * 36;
            s_w[r * 65 + oc] = w[(oc0 + oc) * 4608 + icb * 36 + r];
        }
        // features: 12 rows (4ic x 3ky) x 128 px, stored at offset +1
#pragma unroll
        for (int k = 0; k < 12; k++) {
            int idx = t + 128 * k;
            int icr = idx >> 7;
            int x = idx & 127;
            int icL = icr / 3;
            int ky = icr - icL * 3;
            int gy = y + ky - 1;
            float v = 0.f;
            if (gy >= 0 && gy < 128) v = feat[(icb * 4 + icL) * HW + gy * 128 + x];
            s_f[icr * 130 + x + 1] = v;
        }
        if (t < 12) { s_f[t * 130] = 0.f; s_f[t * 130 + 129] = 0.f; }
        __syncthreads();

#pragma unroll 4
        for (int icr = 0; icr < 12; icr++) {
            float f0[8], f1[8], f2[8];
            int fb = icr * 130 + tx;
#pragma unroll
            for (int j = 0; j < 8; j++) {
                f0[j] = s_f[fb + 16 * j];
                f1[j] = s_f[fb + 16 * j + 1];
                f2[j] = s_f[fb + 16 * j + 2];
            }
            int wb = 3 * icr * 65 + toc;
#pragma unroll
            for (int i = 0; i < 8; i++) {
                float w0 = s_w[wb + 8 * i];
                float w1 = s_w[wb + 65 + 8 * i];
                float w2 = s_w[wb + 130 + 8 * i];
                if (icr < 6) {
#pragma unroll
                    for (int j = 0; j < 8; j++) {
                        accA[i][j] = fmaf(w0, f0[j], accA[i][j]);
                        accA[i][j] = fmaf(w1, f1[j], accA[i][j]);
                        accA[i][j] = fmaf(w2, f2[j], accA[i][j]);
                    }
                } else {
#pragma unroll
                    for (int j = 0; j < 8; j++) {
                        accB[i][j] = fmaf(w0, f0[j], accB[i][j]);
                        accB[i][j] = fmaf(w1, f1[j], accB[i][j]);
                        accB[i][j] = fmaf(w2, f2[j], accB[i][j]);
                    }
                }
            }
        }
        __syncthreads();
    }
#pragma unroll
    for (int i = 0; i < 8; i++) {
        int oc = oc0 + toc + 8 * i;
        float b = bias[oc];
#pragma unroll
        for (int j = 0; j < 8; j++) {
            float v = (accA[i][j] + accB[i][j]) + b;
            g_rpn[oc * HW + y * 128 + tx + 16 * j] = fmaxf(v, 0.f);
        }
    }
}

// 1x1 cls head (512->9) in FP64 + sigmoid + coarse 16-bit histogram. grid 128, block 128.
// VERBATIM from the R10 passing kernel — load-bearing for the knife-edge decisions.
__global__ __launch_bounds__(128) void k_cls(const float* __restrict__ cw,
                                             const float* __restrict__ cb) {
    __shared__ double s_cw[512 * 9];
    int y = blockIdx.x, x = threadIdx.x;
#pragma unroll
    for (int k = 0; k < 36; k++) {
        int idx = x + 128 * k;
        int a = idx >> 9, c = idx & 511;
        s_cw[c * 9 + a] = (double)cw[idx];
    }
    __syncthreads();
    double acc[9];
#pragma unroll
    for (int a = 0; a < 9; a++) acc[a] = (double)cb[a];
    int pos = y * 128 + x;
#pragma unroll 2
    for (int c = 0; c < 512; c++) {
        double v = (double)g_rpn[c * HW + pos];
#pragma unroll
        for (int a = 0; a < 9; a++) acc[a] = fma(v, s_cw[c * 9 + a], acc[a]);
    }
#pragma unroll
    for (int a = 0; a < 9; a++) {
        float s = (float)(1.0 / (1.0 + exp(-acc[a])));
        g_score[pos * 9 + a] = s;
        atomicAdd(&g_hist[__float_as_uint(s) >> 16], 1);
    }
}

// coarse pass: parallel suffix-scan to find the 16-bit bucket containing rank 2000.
__global__ __launch_bounds__(1024) void k_thresh() {
    __shared__ int s_c[1024];
    __shared__ int warp_tot[32];
    int t = threadIdx.x;
    const int4* p = (const int4*)g_hist + t * 16;
    int s = 0;
#pragma unroll
    for (int i = 0; i < 16; i++) { int4 v = p[i]; s += v.x + v.y + v.z + v.w; }
    s_c[t] = s;
    __syncthreads();
    int k = 1023 - t;
    int val = s_c[k];
    int lane = t & 31, wid = t >> 5;
#pragma unroll
    for (int o = 1; o < 32; o <<= 1) {
        int n = __shfl_up_sync(0xFFFFFFFFu, val, o);
        if (lane >= o) val += n;
    }
    if (lane == 31) warp_tot[wid] = val;
    __syncthreads();
    if (wid == 0) {
        int wv = warp_tot[lane];
#pragma unroll
        for (int o = 1; o < 32; o <<= 1) {
            int n = __shfl_up_sync(0xFFFFFFFFu, wv, o);
            if (lane >= o) wv += n;
        }
        warp_tot[lane] = wv;
    }
    __syncthreads();
    int S_incl = val + (wid > 0 ? warp_tot[wid - 1] : 0);
    int S_next = S_incl - s_c[k];
    if (S_incl >= 2000 && S_next < 2000) {
        int a2 = S_next;
        unsigned B = 0;
        for (int b = 63; b >= 0; b--) {
            int c = g_hist[k * 64 + b];
            if (a2 + c >= 2000) { B = (unsigned)(k * 64 + b); break; }
            a2 += c;
        }
        g_b16 = B; g_cntabove = a2;
    }
}

// fine pass: histogram low 16 bits within the boundary bucket.
__global__ void k_hist2() {
    int idx = blockIdx.x * 256 + threadIdx.x;
    if (idx >= N_ANCH) return;
    unsigned bits = __float_as_uint(g_score[idx]);
    if ((bits >> 16) == g_b16) atomicAdd(&g_hist2[bits & 0xFFFFu], 1);
}

// refine to exact 32-bit threshold (parallel suffix-scan).
__global__ __launch_bounds__(1024) void k_thresh2() {
    __shared__ int s_c[1024];
    __shared__ int warp_tot[32];
    int t = threadIdx.x;
    const int4* p = (const int4*)g_hist2 + t * 16;
    int s = 0;
#pragma unroll
    for (int i = 0; i < 16; i++) { int4 v = p[i]; s += v.x + v.y + v.z + v.w; }
    s_c[t] = s;
    __syncthreads();
    int k = 1023 - t;
    int val = s_c[k];
    int lane = t & 31, wid = t >> 5;
#pragma unroll
    for (int o = 1; o < 32; o <<= 1) {
        int n = __shfl_up_sync(0xFFFFFFFFu, val, o);
        if (lane >= o) val += n;
    }
    if (lane == 31) warp_tot[wid] = val;
    __syncthreads();
    if (wid == 0) {
        int wv = warp_tot[lane];
#pragma unroll
        for (int o = 1; o < 32; o <<= 1) {
            int n = __shfl_up_sync(0xFFFFFFFFu, wv, o);
            if (lane >= o) wv += n;
        }
        warp_tot[lane] = wv;
    }
    __syncthreads();
    int target = 2000 - g_cntabove;
    int S_incl = val + (wid > 0 ? warp_tot[wid - 1] : 0);
    int S_next = S_incl - s_c[k];
    if (S_incl >= target && S_next < target) {
        int a2 = S_next;
        unsigned L = 0;
        for (int b = 63; b >= 0; b--) {
            int c = g_hist2[k * 64 + b];
            if (a2 + c >= target) { L = (unsigned)(k * 64 + b); break; }
            a2 += c;
        }
        g_thr32 = (g_b16 << 16) | L;
    }
}

__global__ void k_gather() {
    int idx = blockIdx.x * 256 + threadIdx.x;
    if (idx >= N_ANCH) return;
    unsigned bits = __float_as_uint(g_score[idx]);
    if (bits >= g_thr32) {
        int p = atomicAdd(&g_candcnt, 1);
        if (p < 4096)
            g_cand[p] = ((unsigned long long)bits << 32) | (unsigned)(~(unsigned)idx);
    }
}

__global__ __launch_bounds__(1024) void k_sort() {
    __shared__ unsigned long long s[4096];
    int t = threadIdx.x;
    int cnt = g_candcnt; if (cnt > 4096) cnt = 4096;
    for (int i = t; i < 4096; i += 1024) s[i] = (i < cnt) ? g_cand[i] : 0ULL;
    __syncthreads();
    for (int k = 2; k <= 4096; k <<= 1) {
        for (int j = k >> 1; j > 0; j >>= 1) {
            for (int i = t; i < 4096; i += 1024) {
                int ixj = i ^ j;
                if (ixj > i) {
                    unsigned long long a = s[i], b = s[ixj];
                    bool up = (i & k) == 0;
                    if (up ? (a < b) : (a > b)) { s[i] = b; s[ixj] = a; }
                }
            }
            __syncthreads();
        }
    }
    for (int r = t; r < 2000; r += 1024) {
        unsigned long long key = s[r];
        g_selscore[r] = __uint_as_float((unsigned)(key >> 32));
        g_selidx[r] = (int)(~(unsigned)key);
    }
}

// per-selected-box: FP64 4x 512-dot (box head) + exact-f32 anchor decode chain
__global__ __launch_bounds__(256) void k_decode(const float* __restrict__ bw,
                                                const float* __restrict__ bb) {
    int warp = threadIdx.x >> 5;
    int lane = threadIdx.x & 31;
    int r = blockIdx.x * 8 + warp;
    if (r >= 2000) return;
    int idx = g_selidx[r];
    int pidx = idx / 9;
    int a = idx - pidx * 9;
    const float* w0 = bw + (4 * a + 0) * 512;
    const float* w1 = bw + (4 * a + 1) * 512;
    const float* w2 = bw + (4 * a + 2) * 512;
    const float* w3 = bw + (4 * a + 3) * 512;
    double s0 = 0.0, s1 = 0.0, s2 = 0.0, s3 = 0.0;
    for (int c = lane; c < 512; c += 32) {
        double v = (double)g_rpn[c * HW + pidx];
        s0 = fma(v, (double)w0[c], s0);
        s1 = fma(v, (double)w1[c], s1);
        s2 = fma(v, (double)w2[c], s2);
        s3 = fma(v, (double)w3[c], s3);
    }
#pragma unroll
    for (int o = 16; o > 0; o >>= 1) {
        s0 += __shfl_xor_sync(0xFFFFFFFFu, s0, o);
        s1 += __shfl_xor_sync(0xFFFFFFFFu, s1, o);
        s2 += __shfl_xor_sync(0xFFFFFFFFu, s2, o);
        s3 += __shfl_xor_sync(0xFFFFFFFFu, s3, o);
    }
    if (lane == 0) {
        float dx = (float)(s0 + (double)bb[4 * a + 0]);
        float dy = (float)(s1 + (double)bb[4 * a + 1]);
        float dw = (float)(s2 + (double)bb[4 * a + 2]);
        float dh = (float)(s3 + (double)bb[4 * a + 3]);
        int ari = a / 3, si = a - ari * 3;
        float arf = (ari == 0) ? 0.5f : ((ari == 1) ? 1.0f : 2.0f);
        float scf = (si == 0) ? 128.f : ((si == 1) ? 256.f : 512.f);
        float h_r = __fsqrt_rn(arf);
        float w_r = __fdiv_rn(1.0f, h_r);
        float ws = __fmul_rn(w_r, scf), hs = __fmul_rn(h_r, scf);
        float bx1 = rintf(__fmul_rn(-0.5f, ws)), bx2 = rintf(__fmul_rn(0.5f, ws));
        float by1 = rintf(__fmul_rn(-0.5f, hs)), by2 = rintf(__fmul_rn(0.5f, hs));
        int gy = pidx >> 7, gx = pidx & 127;
        float sx = (float)(gx * 16), sy = (float)(gy * 16);
        float x1 = __fadd_rn(sx, bx1), y1 = __fadd_rn(sy, by1);
        float x2 = __fadd_rn(sx, bx2), y2 = __fadd_rn(sy, by2);
        float aw = __fsub_rn(x2, x1), ah = __fsub_rn(y2, y1);
        float acx = __fadd_rn(x1, __fmul_rn(0.5f, aw));
        float acy = __fadd_rn(y1, __fmul_rn(0.5f, ah));
        const float BCLIP = 4.135166556742356f;
        dw = fminf(dw, BCLIP);
        dh = fminf(dh, BCLIP);
        float pcx = __fadd_rn(__fmul_rn(dx, aw), acx);
        float pcy = __fadd_rn(__fmul_rn(dy, ah), acy);
        float ew = (float)exp((double)dw);
        float eh = (float)exp((double)dh);
        float pw = __fmul_rn(ew, aw);
        float ph = __fmul_rn(eh, ah);
        float x1p = __fsub_rn(pcx, __fmul_rn(0.5f, pw));
        float y1p = __fsub_rn(pcy, __fmul_rn(0.5f, ph));
        float x2p = __fadd_rn(pcx, __fmul_rn(0.5f, pw));
        float y2p = __fadd_rn(pcy, __fmul_rn(0.5f, ph));
        float x1c = fminf(fmaxf(x1p, 0.f), 2048.f);
        float y1c = fminf(fmaxf(y1p, 0.f), 2048.f);
        float x2c = fminf(fmaxf(x2p, 0.f), 2048.f);
        float y2c = fminf(fmaxf(y2p, 0.f), 2048.f);
        float wsz = __fsub_rn(x2c, x1c), hsz = __fsub_rn(y2c, y1c);
        g_props[r * 4 + 0] = x1c;
        g_props[r * 4 + 1] = y1c;
        g_props[r * 4 + 2] = x2c;
        g_props[r * 4 + 3] = y2c;
        g_area[r] = __fmul_rn(wsz, hsz);
        if (wsz >= 16.0f && hsz >= 16.0f)
            atomicOr(&g_validw[r >> 5], 1u << (r & 31));
    }
}

// 2000x2000 IoU>0.7 bitmatrix, exact f32 op chain. grid(63,63), block(32,32).
__global__ void k_iou() {
    __shared__ float4 sbi[32], sbj[32];
    __shared__ float sai[32], saj[32];
    int tx = threadIdx.x, ty = threadIdx.y;
    int i0 = blockIdx.y * 32, j0 = blockIdx.x * 32;
    if (ty == 0) { sbj[tx] = ((const float4*)g_props)[j0 + tx]; saj[tx] = g_area[j0 + tx]; }
    if (ty == 1) { sbi[tx] = ((const float4*)g_props)[i0 + tx]; sai[tx] = g_area[i0 + tx]; }
    __syncthreads();
    float4 bi = sbi[ty], bj = sbj[tx];
    float x1 = fmaxf(bi.x, bj.x), y1 = fmaxf(bi.y, bj.y);
    float x2 = fminf(bi.z, bj.z), y2 = fminf(bi.w, bj.w);
    float iw_ = fmaxf(__fsub_rn(x2, x1), 0.f);
    float ih_ = fmaxf(__fsub_rn(y2, y1), 0.f);
    float inter = __fmul_rn(iw_, ih_);
    float uni = fmaxf(__fsub_rn(__fadd_rn(sai[ty], saj[tx]), inter), 1e-9f);
    unsigned m = __ballot_sync(0xFFFFFFFFu, __fdiv_rn(inter, uni) > 0.7f);
    if (tx == 0) g_supmask[(i0 + ty) * 64 + blockIdx.x] = m;
}

// sequential greedy NMS on bitmatrix; one warp, keep mask in registers.
__global__ void k_nms() {
    int lane = threadIdx.x;
    unsigned keep0 = 0, keep1 = 0;
    unsigned valid0 = g_validw[lane], valid1 = g_validw[lane + 32];
    unsigned sup0 = g_supmask[lane], sup1 = g_supmask[lane + 32];
    for (int i = 0; i < 2000; i++) {
        unsigned n0 = 0, n1 = 0;
        if (i < 1999) {
            n0 = g_supmask[(i + 1) * 64 + lane];
            n1 = g_supmask[(i + 1) * 64 + lane + 32];
        }
        int w = i >> 5;
        unsigned bmask = (1u << (i & 31)) - 1u;
        unsigned below0 = (lane < w) ? 0xFFFFFFFFu : ((lane == w) ? bmask : 0u);
        unsigned below1 = ((lane + 32) < w) ? 0xFFFFFFFFu : (((lane + 32) == w) ? bmask : 0u);
        unsigned tbits = (sup0 & keep0 & below0) | (sup1 & keep1 & below1);
        bool suppressed = __any_sync(0xFFFFFFFFu, tbits != 0u);
        if (!suppressed) {
            unsigned bit = 1u << (i & 31);
            if (w < 32) { if (lane == w && (valid0 & bit)) keep0 |= bit; }
            else        { if (lane == w - 32 && (valid1 & bit)) keep1 |= bit; }
        }
        sup0 = n0; sup1 = n1;
    }
    g_keepw[lane] = keep0;
    g_keepw[lane + 32] = keep1;
    int c = __popc(keep0) + __popc(keep1);
#pragma unroll
    for (int o = 16; o > 0; o >>= 1) c += __shfl_xor_sync(0xFFFFFFFFu, c, o);
    if (lane == 0) g_keepcnt = c;
}

// compact kept boxes into output: props[0..4000), scores[4000..5000)
__global__ __launch_bounds__(1024) void k_final(float* __restrict__ out) {
    __shared__ int pre[64];
    __shared__ unsigned kw[64];
    int t = threadIdx.x;
    if (t < 64) kw[t] = g_keepw[t];
    __syncthreads();
    if (t == 0) {
        int acc = 0;
        for (int wds = 0; wds < 64; wds++) { pre[wds] = acc; acc += __popc(kw[wds]); }
    }
    __syncthreads();
    int K = g_keepcnt;
    for (int r = t; r < 2000; r += 1024) {
        int w = r >> 5, b = r & 31;
        if ((kw[w] >> b) & 1u) {
            int rank = pre[w] + __popc(kw[w] & ((1u << b) - 1u));
            if (rank < 1000) {
                out[rank * 4 + 0] = g_props[r * 4 + 0];
                out[rank * 4 + 1] = g_props[r * 4 + 1];
                out[rank * 4 + 2] = g_props[r * 4 + 2];
                out[rank * 4 + 3] = g_props[r * 4 + 3];
                out[4000 + rank] = g_selscore[r];
            }
        }
    }
    for (int k = t; k < 1000; k += 1024) {
        if (k >= K) {
            out[k * 4 + 0] = 0.f;
            out[k * 4 + 1] = 0.f;
            out[k * 4 + 2] = 0.f;
            out[k * 4 + 3] = 0.f;
            out[4000 + k] = -1.0f;
        }
    }
}

extern "C" void kernel_launch(void* const* d_in, const int* in_sizes, int n_in,
                              void* d_out, int out_size) {
    const float* feat   = (const float*)d_in[1];
    const float* conv_w = (const float*)d_in[2];
    const float* conv_b = (const float*)d_in[3];
    const float* cls_w  = (const float*)d_in[4];
    const float* cls_b  = (const float*)d_in[5];
    const float* box_w  = (const float*)d_in[6];
    const float* box_b  = (const float*)d_in[7];
    float* out = (float*)d_out;

    k_init<<<64, 1024>>>();
    // 2 no-op launches so k_conv is the 4th launch (the one ncu captures)
    k_nop<<<1, 32>>>();
    k_nop<<<1, 32>>>();
    k_conv<<<dim3(128, 8), 128>>>(feat, conv_w, conv_b);
    k_cls<<<128, 128>>>(cls_w, cls_b);
    k_thresh<<<1, 1024>>>();
    k_hist2<<<(N_ANCH + 255) / 256, 256>>>();
    k_thresh2<<<1, 1024>>>();
    k_gather<<<(N_ANCH + 255) / 256, 256>>>();
    k_sort<<<1, 1024>>>();
    k_decode<<<250, 256>>>(box_w, box_b);
    k_iou<<<dim3(63, 63), dim3(32, 32)>>>();
    k_nms<<<1, 32>>>();
    k_final<<<1, 1024>>>(out);
}